// round 6
// baseline (speedup 1.0000x reference)
#include <cuda_runtime.h>

// ---------------------------------------------------------------------------
// RelativeAgentPositionEmbedding — fp32 CUDA-core kernel with f32x2 FFMA.
//
// Structure per CTA (512 threads, 128 edges):
//   1. compute 6 features per edge (gathers + trig), store in smem
//   2. for d in 0..5:
//        stage W1[d] (65x128) + W2[d] (128x128) + b1/lnw/lnb/b2 into smem
//        per warp (8 edges): build x[65] per edge in smem (transposed [k][e])
//        GEMM1: h = x @ W1 + b1          (f32x2 over edge pairs)
//        LayerNorm over 128 + ReLU       (warp shuffles, warp-local)
//        store h transposed [ch][e] in smem
//        GEMM2: acc += relu(h) @ W2 + b2 (f32x2 over edge pairs)
//   3. store acc -> out[e][0..127]
// ---------------------------------------------------------------------------

#define E_TOTAL   500000
#define DIMS      6
#define HID       128
#define NFREQ     32
#define KDIM      65          // 2*NFREQ + 1
#define TILE      128         // edges per CTA
#define NTHREADS  512
#define EPW       8           // edges per warp
#define LN_EPS_F  1e-5f
#define TWO_PI_F  6.283185307179586f
#define PI_F      3.14159265358979323846f

// shared memory layout (float offsets)
#define OFF_FREQS 0                         // 192
#define OFF_FEAT  (OFF_FREQS + DIMS*NFREQ)  // TILE*8 (stride 8 per edge)
#define OFF_W1    (OFF_FEAT + TILE*8)       // 65*128
#define OFF_W2    (OFF_W1 + KDIM*HID)       // 128*128
#define OFF_B1    (OFF_W2 + HID*HID)        // 128
#define OFF_LNW   (OFF_B1 + HID)            // 128
#define OFF_LNB   (OFF_LNW + HID)           // 128
#define OFF_B2    (OFF_LNB + HID)           // 128
#define OFF_X     (OFF_B2 + HID)            // 65*TILE   layout [k][e]
#define OFF_H     (OFF_X + KDIM*TILE)       // 128*TILE  layout [ch][e]
#define SMEM_FLOATS (OFF_H + HID*TILE)      // 51136 floats = 204544 B

typedef unsigned long long ull;

__device__ int g_edge_is64;

// ---- f32x2 helpers (packed two-lane fp32, sm_100+) ------------------------
__device__ __forceinline__ ull pack2(float lo, float hi) {
    ull r; asm("mov.b64 %0, {%1,%2};" : "=l"(r) : "f"(lo), "f"(hi)); return r;
}
__device__ __forceinline__ ull dup2(float v) { return pack2(v, v); }
__device__ __forceinline__ void unpack2(ull v, float& lo, float& hi) {
    asm("mov.b64 {%0,%1}, %2;" : "=f"(lo), "=f"(hi) : "l"(v));
}
__device__ __forceinline__ ull fma2(ull a, ull b, ull c) {
    ull d; asm("fma.rn.f32x2 %0, %1, %2, %3;" : "=l"(d) : "l"(a), "l"(b), "l"(c)); return d;
}
__device__ __forceinline__ ull add2(ull a, ull b) {
    ull d; asm("add.rn.f32x2 %0, %1, %2;" : "=l"(d) : "l"(a), "l"(b)); return d;
}
__device__ __forceinline__ ull mul2(ull a, ull b) {
    ull d; asm("mul.rn.f32x2 %0, %1, %2;" : "=l"(d) : "l"(a), "l"(b)); return d;
}

// Detect whether the edge buffer is int64 (ref code asks for int64, but JAX
// without x64 silently gives int32). Node ids < 50000, so if int64 every
// high 32-bit word of the first 256 entries is 0. If the buffer is int32,
// those words are random node ids — probability all 256 are zero is ~0.
__global__ void detect_edge_dtype_kernel(const int2* __restrict__ edge) {
    if (threadIdx.x == 0 && blockIdx.x == 0) {
        int all0 = 1;
        for (int i = 0; i < 256; i++) {
            if (edge[i].y != 0) { all0 = 0; break; }
        }
        g_edge_is64 = all0;
    }
}

// one f32x2 GEMM micro-step: 4 channels x 4 edge-pairs (=32 MACs/lane)
#define GSTEP(ACC, XOFF, WOFF)                                              \
    {                                                                       \
        const float4 w = *(const float4*)&sm[(WOFF) + lane4];               \
        ull wd0 = dup2(w.x), wd1 = dup2(w.y), wd2 = dup2(w.z), wd3 = dup2(w.w); \
        ull xp0 = *(const ull*)&sm[(XOFF) + ebase + 0];                     \
        ull xp1 = *(const ull*)&sm[(XOFF) + ebase + 2];                     \
        ull xp2 = *(const ull*)&sm[(XOFF) + ebase + 4];                     \
        ull xp3 = *(const ull*)&sm[(XOFF) + ebase + 6];                     \
        ACC[0][0] = fma2(wd0, xp0, ACC[0][0]);                              \
        ACC[1][0] = fma2(wd1, xp0, ACC[1][0]);                              \
        ACC[2][0] = fma2(wd2, xp0, ACC[2][0]);                              \
        ACC[3][0] = fma2(wd3, xp0, ACC[3][0]);                              \
        ACC[0][1] = fma2(wd0, xp1, ACC[0][1]);                              \
        ACC[1][1] = fma2(wd1, xp1, ACC[1][1]);                              \
        ACC[2][1] = fma2(wd2, xp1, ACC[2][1]);                              \
        ACC[3][1] = fma2(wd3, xp1, ACC[3][1]);                              \
        ACC[0][2] = fma2(wd0, xp2, ACC[0][2]);                              \
        ACC[1][2] = fma2(wd1, xp2, ACC[1][2]);                              \
        ACC[2][2] = fma2(wd2, xp2, ACC[2][2]);                              \
        ACC[3][2] = fma2(wd3, xp2, ACC[3][2]);                              \
        ACC[0][3] = fma2(wd0, xp3, ACC[0][3]);                              \
        ACC[1][3] = fma2(wd1, xp3, ACC[1][3]);                              \
        ACC[2][3] = fma2(wd2, xp3, ACC[2][3]);                              \
        ACC[3][3] = fma2(wd3, xp3, ACC[3][3]);                              \
    }

__global__ __launch_bounds__(NTHREADS, 1)
void rape_kernel(const float* __restrict__ srcN, const float* __restrict__ tgtN,
                 const void* __restrict__ edgeRaw,
                 const float* __restrict__ freqs,
                 const float* __restrict__ W1, const float* __restrict__ b1,
                 const float* __restrict__ lnw, const float* __restrict__ lnb,
                 const float* __restrict__ W2, const float* __restrict__ b2,
                 float* __restrict__ out)
{
    extern __shared__ float sm[];
    const int tid   = threadIdx.x;
    const int lane  = tid & 31;
    const int warp  = tid >> 5;
    const int lane4 = lane * 4;
    const int tileBase = blockIdx.x * TILE;
    const int ebase = warp * EPW;   // this warp's local edge base (0..120)

    // ---- stage freqs -------------------------------------------------------
    if (tid < DIMS * NFREQ) sm[OFF_FREQS + tid] = freqs[tid];

    // ---- per-edge features -------------------------------------------------
    if (tid < TILE) {
        int e  = tileBase + tid;
        int ec = (e < E_TOTAL) ? e : (E_TOTAL - 1);
        long long si, ti;
        if (g_edge_is64) {
            const long long* ep = (const long long*)edgeRaw;
            si = ep[ec];
            ti = ep[E_TOTAL + ec];
        } else {
            const int* ep = (const int*)edgeRaw;
            si = ep[ec];
            ti = ep[E_TOTAL + ec];
        }
        const float* S = srcN + si * 5;
        const float* T = tgtN + ti * 5;
        float spx = S[0], spy = S[1], shd = S[2], ssp = S[3];
        float tpx = T[0], tpy = T[1], thd = T[2], tsp = T[3];

        float dx = spx - tpx, dy = spy - tpy;
        float dist = sqrtf(dx * dx + dy * dy);
        float is_close = (dist < 3.0f) ? 1.0f : 0.0f;
        float ang = atan2f(dy, dx);
        // wrap_angle with python-style mod (sign of divisor)
        float wa = shd - thd + PI_F;
        float m = fmodf(wa, TWO_PI_F);
        if (m < 0.0f) m += TWO_PI_F;
        float dh = m - PI_F;

        float sa, ca;   __sincosf(ang, &sa, &ca);
        float sth, cth; __sincosf(thd, &sth, &cth);
        float ssh, csh; __sincosf(shd, &ssh, &csh);
        float t_close = tsp * (cth * ca + sth * sa);
        float s_close = ssp * (csh * ca + ssh * sa);

        float* f = &sm[OFF_FEAT + tid * 8];
        f[0] = dx; f[1] = dy; f[2] = dh; f[3] = is_close; f[4] = t_close; f[5] = s_close;
    }

    // ---- output accumulators: acc[channel][edge-pair] ----------------------
    ull acc[4][4];
    #pragma unroll
    for (int c = 0; c < 4; c++)
        #pragma unroll
        for (int p = 0; p < 4; p++)
            acc[c][p] = pack2(0.0f, 0.0f);

    for (int d = 0; d < DIMS; d++) {
        __syncthreads();   // prev-dim GEMM2 done with W2 smem; feat ready (d==0)

        // ---- stage weights for this input dim ------------------------------
        {
            const float4* g1 = (const float4*)(W1 + (size_t)d * KDIM * HID);
            float4* s1 = (float4*)&sm[OFF_W1];
            #pragma unroll 2
            for (int i = tid; i < (KDIM * HID) / 4; i += NTHREADS) s1[i] = g1[i];
            const float4* g2 = (const float4*)(W2 + (size_t)d * HID * HID);
            float4* s2 = (float4*)&sm[OFF_W2];
            #pragma unroll 2
            for (int i = tid; i < (HID * HID) / 4; i += NTHREADS) s2[i] = g2[i];
            if (tid < HID) {
                sm[OFF_B1  + tid] = b1[d * HID + tid];
                sm[OFF_LNW + tid] = lnw[d * HID + tid];
                sm[OFF_LNB + tid] = lnb[d * HID + tid];
                sm[OFF_B2  + tid] = b2[d * HID + tid];
            }
        }

        // ---- build x[k][e] for this warp's 8 edges -------------------------
        // items: 8 edges x 33 slots (32 sincos pairs + 1 passthrough)
        for (int idx = lane; idx < EPW * 33; idx += 32) {
            int el = idx / 33;
            int j  = idx - el * 33;
            float f = sm[OFF_FEAT + (ebase + el) * 8 + d];
            if (j < NFREQ) {
                float th2 = f * sm[OFF_FREQS + d * NFREQ + j] * TWO_PI_F;
                float s, c; __sincosf(th2, &s, &c);
                sm[OFF_X + j * TILE + ebase + el]           = c;
                sm[OFF_X + (NFREQ + j) * TILE + ebase + el] = s;
            } else {
                sm[OFF_X + 2 * NFREQ * TILE + ebase + el]   = f;
            }
        }
        __syncthreads();   // weights staged + x visible

        // ---- GEMM1: h = x @ W1[d] + b1[d] ----------------------------------
        ull hacc[4][4];
        #pragma unroll
        for (int c = 0; c < 4; c++) {
            ull bd = dup2(sm[OFF_B1 + lane4 + c]);
            #pragma unroll
            for (int p = 0; p < 4; p++) hacc[c][p] = bd;
        }
        #pragma unroll 8
        for (int k = 0; k < 64; k++) {
            GSTEP(hacc, OFF_X + k * TILE, OFF_W1 + k * HID);
        }
        GSTEP(hacc, OFF_X + 64 * TILE, OFF_W1 + 64 * HID);

        // ---- LayerNorm (per edge over 128 channels) ------------------------
        float s_lo[4], s_hi[4], q_lo[4], q_hi[4];
        #pragma unroll
        for (int p = 0; p < 4; p++) {
            ull s = hacc[0][p];
            ull q = mul2(hacc[0][p], hacc[0][p]);
            #pragma unroll
            for (int c = 1; c < 4; c++) {
                s = add2(s, hacc[c][p]);
                q = fma2(hacc[c][p], hacc[c][p], q);
            }
            unpack2(s, s_lo[p], s_hi[p]);
            unpack2(q, q_lo[p], q_hi[p]);
        }
        #pragma unroll
        for (int o = 16; o > 0; o >>= 1) {
            #pragma unroll
            for (int p = 0; p < 4; p++) {
                s_lo[p] += __shfl_xor_sync(0xffffffffu, s_lo[p], o);
                s_hi[p] += __shfl_xor_sync(0xffffffffu, s_hi[p], o);
                q_lo[p] += __shfl_xor_sync(0xffffffffu, q_lo[p], o);
                q_hi[p] += __shfl_xor_sync(0xffffffffu, q_hi[p], o);
            }
        }
        float mu_lo[4], mu_hi[4], rs_lo[4], rs_hi[4];
        #pragma unroll
        for (int p = 0; p < 4; p++) {
            const float inv = 1.0f / (float)HID;
            mu_lo[p] = s_lo[p] * inv;
            mu_hi[p] = s_hi[p] * inv;
            float v0 = q_lo[p] * inv - mu_lo[p] * mu_lo[p];
            float v1 = q_hi[p] * inv - mu_hi[p] * mu_hi[p];
            rs_lo[p] = rsqrtf(v0 + LN_EPS_F);
            rs_hi[p] = rsqrtf(v1 + LN_EPS_F);
        }

        // ---- normalize + relu, store h transposed [ch][e] ------------------
        #pragma unroll
        for (int c = 0; c < 4; c++) {
            float w_ = sm[OFF_LNW + lane4 + c];
            float b_ = sm[OFF_LNB + lane4 + c];
            #pragma unroll
            for (int p = 0; p < 4; p++) {
                float lo, hi; unpack2(hacc[c][p], lo, hi);
                float nlo = fmaxf(fmaf((lo - mu_lo[p]) * rs_lo[p], w_, b_), 0.0f);
                float nhi = fmaxf(fmaf((hi - mu_hi[p]) * rs_hi[p], w_, b_), 0.0f);
                *(ull*)&sm[OFF_H + (lane4 + c) * TILE + ebase + 2 * p] = pack2(nlo, nhi);
            }
        }
        __syncwarp();  // h written by all lanes of this warp before reads

        // ---- GEMM2: acc += relu(h) @ W2[d] + b2[d] -------------------------
        #pragma unroll
        for (int c = 0; c < 4; c++) {
            ull bd = dup2(sm[OFF_B2 + lane4 + c]);
            #pragma unroll
            for (int p = 0; p < 4; p++) acc[c][p] = add2(acc[c][p], bd);
        }
        #pragma unroll 8
        for (int k = 0; k < HID; k++) {
            GSTEP(acc, OFF_H + k * TILE, OFF_W2 + k * HID);
        }
    }

    // ---- store: out[e][lane4 + 0..3] for each of 8 edges -------------------
    #pragma unroll
    for (int p = 0; p < 4; p++) {
        float lo0, hi0, lo1, hi1, lo2, hi2, lo3, hi3;
        unpack2(acc[0][p], lo0, hi0);
        unpack2(acc[1][p], lo1, hi1);
        unpack2(acc[2][p], lo2, hi2);
        unpack2(acc[3][p], lo3, hi3);
        int e0 = tileBase + ebase + 2 * p;
        int e1 = e0 + 1;
        if (e0 < E_TOTAL) {
            float4 v = make_float4(lo0, lo1, lo2, lo3);
            *(float4*)&out[(size_t)e0 * HID + lane4] = v;
        }
        if (e1 < E_TOTAL) {
            float4 v = make_float4(hi0, hi1, hi2, hi3);
            *(float4*)&out[(size_t)e1 * HID + lane4] = v;
        }
    }
}

extern "C" void kernel_launch(void* const* d_in, const int* in_sizes, int n_in,
                              void* d_out, int out_size) {
    (void)in_sizes; (void)n_in; (void)out_size;
    const float* srcN  = (const float*)d_in[0];
    const float* tgtN  = (const float*)d_in[1];
    const void*  edge  = d_in[2];
    const float* freqs = (const float*)d_in[3];
    const float* W1    = (const float*)d_in[4];
    const float* b1    = (const float*)d_in[5];
    const float* lnw   = (const float*)d_in[6];
    const float* lnb   = (const float*)d_in[7];
    const float* W2    = (const float*)d_in[8];
    const float* b2    = (const float*)d_in[9];
    float* out = (float*)d_out;

    cudaFuncSetAttribute(rape_kernel,
                         cudaFuncAttributeMaxDynamicSharedMemorySize,
                         SMEM_FLOATS * (int)sizeof(float));

    detect_edge_dtype_kernel<<<1, 32>>>((const int2*)edge);

    int grid = (E_TOTAL + TILE - 1) / TILE;
    rape_kernel<<<grid, NTHREADS, SMEM_FLOATS * sizeof(float)>>>(
        srcN, tgtN, edge, freqs, W1, b1, lnw, lnb, W2, b2, out);
}

// round 17
// speedup vs baseline: 1.0573x; 1.0573x over previous
#include <cuda_runtime.h>

// ---------------------------------------------------------------------------
// RelativeAgentPositionEmbedding — fp32 CUDA-core kernel with f32x2 FFMA.
// R15: x operand loads switched LDS.64x4 -> LDS.128x2 (crossbar 8->6
// phases/warp/step; kernel flips from L1-bound (86%) to fma-bound).
// NOTE: tcgen05 is unusable here — harness builds via compute_103 PTX which
// rejects all 'a'-target (arch-specific) instructions.
// ---------------------------------------------------------------------------

#define E_TOTAL   500000
#define DIMS      6
#define HID       128
#define NFREQ     32
#define KDIM      65
#define TILE      128
#define NTHREADS  512
#define EPW       8
#define LN_EPS_F  1e-5f
#define TWO_PI_F  6.283185307179586f
#define PI_F      3.14159265358979323846f

#define OFF_FREQS 0
#define OFF_FEAT  (OFF_FREQS + DIMS*NFREQ)
#define OFF_W1    (OFF_FEAT + TILE*8)
#define OFF_W2    (OFF_W1 + KDIM*HID)
#define OFF_B1    (OFF_W2 + HID*HID)
#define OFF_LNW   (OFF_B1 + HID)
#define OFF_LNB   (OFF_LNW + HID)
#define OFF_B2    (OFF_LNB + HID)
#define OFF_X     (OFF_B2 + HID)
#define OFF_H     (OFF_X + KDIM*TILE)
#define SMEM_FLOATS (OFF_H + HID*TILE)   // 51136 floats = 204544 B

typedef unsigned long long ull;

__device__ int g_edge_is64;

__device__ __forceinline__ ull pack2(float lo, float hi) {
    ull r; asm("mov.b64 %0, {%1,%2};" : "=l"(r) : "f"(lo), "f"(hi)); return r;
}
__device__ __forceinline__ ull dup2(float v) { return pack2(v, v); }
__device__ __forceinline__ void unpack2(ull v, float& lo, float& hi) {
    asm("mov.b64 {%0,%1}, %2;" : "=f"(lo), "=f"(hi) : "l"(v));
}
__device__ __forceinline__ ull fma2(ull a, ull b, ull c) {
    ull d; asm("fma.rn.f32x2 %0, %1, %2, %3;" : "=l"(d) : "l"(a), "l"(b), "l"(c)); return d;
}
__device__ __forceinline__ ull add2(ull a, ull b) {
    ull d; asm("add.rn.f32x2 %0, %1, %2;" : "=l"(d) : "l"(a), "l"(b)); return d;
}
__device__ __forceinline__ ull mul2(ull a, ull b) {
    ull d; asm("mul.rn.f32x2 %0, %1, %2;" : "=l"(d) : "l"(a), "l"(b)); return d;
}

__global__ void detect_edge_dtype_kernel(const int2* __restrict__ edge) {
    if (threadIdx.x == 0 && blockIdx.x == 0) {
        int all0 = 1;
        for (int i = 0; i < 256; i++) {
            if (edge[i].y != 0) { all0 = 0; break; }
        }
        g_edge_is64 = all0;
    }
}

// one f32x2 GEMM micro-step: 4 channels x 4 edge-pairs (=32 MACs/lane)
// x pairs loaded as 2x LDS.128 broadcast (contiguous 32B) instead of 4x LDS.64
#define GSTEP(ACC, XOFF, WOFF)                                              \
    {                                                                       \
        const float4 w = *(const float4*)&sm[(WOFF) + lane4];               \
        ull wd0 = dup2(w.x), wd1 = dup2(w.y), wd2 = dup2(w.z), wd3 = dup2(w.w); \
        const ulonglong2 xa = *(const ulonglong2*)&sm[(XOFF) + ebase + 0];  \
        const ulonglong2 xb = *(const ulonglong2*)&sm[(XOFF) + ebase + 4];  \
        ull xp0 = xa.x, xp1 = xa.y, xp2 = xb.x, xp3 = xb.y;                 \
        ACC[0][0] = fma2(wd0, xp0, ACC[0][0]);                              \
        ACC[1][0] = fma2(wd1, xp0, ACC[1][0]);                              \
        ACC[2][0] = fma2(wd2, xp0, ACC[2][0]);                              \
        ACC[3][0] = fma2(wd3, xp0, ACC[3][0]);                              \
        ACC[0][1] = fma2(wd0, xp1, ACC[0][1]);                              \
        ACC[1][1] = fma2(wd1, xp1, ACC[1][1]);                              \
        ACC[2][1] = fma2(wd2, xp1, ACC[2][1]);                              \
        ACC[3][1] = fma2(wd3, xp1, ACC[3][1]);                              \
        ACC[0][2] = fma2(wd0, xp2, ACC[0][2]);                              \
        ACC[1][2] = fma2(wd1, xp2, ACC[1][2]);                              \
        ACC[2][2] = fma2(wd2, xp2, ACC[2][2]);                              \
        ACC[3][2] = fma2(wd3, xp2, ACC[3][2]);                              \
        ACC[0][3] = fma2(wd0, xp3, ACC[0][3]);                              \
        ACC[1][3] = fma2(wd1, xp3, ACC[1][3]);                              \
        ACC[2][3] = fma2(wd2, xp3, ACC[2][3]);                              \
        ACC[3][3] = fma2(wd3, xp3, ACC[3][3]);                              \
    }

__global__ __launch_bounds__(NTHREADS, 1)
void rape_kernel(const float* __restrict__ srcN, const float* __restrict__ tgtN,
                 const void* __restrict__ edgeRaw,
                 const float* __restrict__ freqs,
                 const float* __restrict__ W1, const float* __restrict__ b1,
                 const float* __restrict__ lnw, const float* __restrict__ lnb,
                 const float* __restrict__ W2, const float* __restrict__ b2,
                 float* __restrict__ out)
{
    extern __shared__ float sm[];
    const int tid   = threadIdx.x;
    const int lane  = tid & 31;
    const int warp  = tid >> 5;
    const int lane4 = lane * 4;
    const int tileBase = blockIdx.x * TILE;
    const int ebase = warp * EPW;

    if (tid < DIMS * NFREQ) sm[OFF_FREQS + tid] = freqs[tid];

    if (tid < TILE) {
        int e  = tileBase + tid;
        int ec = (e < E_TOTAL) ? e : (E_TOTAL - 1);
        long long si, ti;
        if (g_edge_is64) {
            const long long* ep = (const long long*)edgeRaw;
            si = ep[ec];
            ti = ep[E_TOTAL + ec];
        } else {
            const int* ep = (const int*)edgeRaw;
            si = ep[ec];
            ti = ep[E_TOTAL + ec];
        }
        const float* S = srcN + si * 5;
        const float* T = tgtN + ti * 5;
        float spx = S[0], spy = S[1], shd = S[2], ssp = S[3];
        float tpx = T[0], tpy = T[1], thd = T[2], tsp = T[3];

        float dx = spx - tpx, dy = spy - tpy;
        float dist = sqrtf(dx * dx + dy * dy);
        float is_close = (dist < 3.0f) ? 1.0f : 0.0f;
        float ang = atan2f(dy, dx);
        float wa = shd - thd + PI_F;
        float m = fmodf(wa, TWO_PI_F);
        if (m < 0.0f) m += TWO_PI_F;
        float dh = m - PI_F;

        float sa, ca;   __sincosf(ang, &sa, &ca);
        float sth, cth; __sincosf(thd, &sth, &cth);
        float ssh, csh; __sincosf(shd, &ssh, &csh);
        float t_close = tsp * (cth * ca + sth * sa);
        float s_close = ssp * (csh * ca + ssh * sa);

        float* f = &sm[OFF_FEAT + tid * 8];
        f[0] = dx; f[1] = dy; f[2] = dh; f[3] = is_close; f[4] = t_close; f[5] = s_close;
    }

    ull acc[4][4];
    #pragma unroll
    for (int c = 0; c < 4; c++)
        #pragma unroll
        for (int p = 0; p < 4; p++)
            acc[c][p] = pack2(0.0f, 0.0f);

    for (int d = 0; d < DIMS; d++) {
        __syncthreads();

        {
            const float4* g1 = (const float4*)(W1 + (size_t)d * KDIM * HID);
            float4* s1 = (float4*)&sm[OFF_W1];
            #pragma unroll 2
            for (int i = tid; i < (KDIM * HID) / 4; i += NTHREADS) s1[i] = g1[i];
            const float4* g2 = (const float4*)(W2 + (size_t)d * HID * HID);
            float4* s2 = (float4*)&sm[OFF_W2];
            #pragma unroll 2
            for (int i = tid; i < (HID * HID) / 4; i += NTHREADS) s2[i] = g2[i];
            if (tid < HID) {
                sm[OFF_B1  + tid] = b1[d * HID + tid];
                sm[OFF_LNW + tid] = lnw[d * HID + tid];
                sm[OFF_LNB + tid] = lnb[d * HID + tid];
                sm[OFF_B2  + tid] = b2[d * HID + tid];
            }
        }

        for (int idx = lane; idx < EPW * 33; idx += 32) {
            int el = idx / 33;
            int j  = idx - el * 33;
            float f = sm[OFF_FEAT + (ebase + el) * 8 + d];
            if (j < NFREQ) {
                float th2 = f * sm[OFF_FREQS + d * NFREQ + j] * TWO_PI_F;
                float s, c; __sincosf(th2, &s, &c);
                sm[OFF_X + j * TILE + ebase + el]           = c;
                sm[OFF_X + (NFREQ + j) * TILE + ebase + el] = s;
            } else {
                sm[OFF_X + 2 * NFREQ * TILE + ebase + el]   = f;
            }
        }
        __syncthreads();

        // ---- GEMM1 ----------------------------------------------------------
        ull hacc[4][4];
        #pragma unroll
        for (int c = 0; c < 4; c++) {
            ull bd = dup2(sm[OFF_B1 + lane4 + c]);
            #pragma unroll
            for (int p = 0; p < 4; p++) hacc[c][p] = bd;
        }
        #pragma unroll 8
        for (int k = 0; k < 64; k++) {
            GSTEP(hacc, OFF_X + k * TILE, OFF_W1 + k * HID);
        }
        GSTEP(hacc, OFF_X + 64 * TILE, OFF_W1 + 64 * HID);

        // ---- LayerNorm ------------------------------------------------------
        float s_lo[4], s_hi[4], q_lo[4], q_hi[4];
        #pragma unroll
        for (int p = 0; p < 4; p++) {
            ull s = hacc[0][p];
            ull q = mul2(hacc[0][p], hacc[0][p]);
            #pragma unroll
            for (int c = 1; c < 4; c++) {
                s = add2(s, hacc[c][p]);
                q = fma2(hacc[c][p], hacc[c][p], q);
            }
            unpack2(s, s_lo[p], s_hi[p]);
            unpack2(q, q_lo[p], q_hi[p]);
        }
        #pragma unroll
        for (int o = 16; o > 0; o >>= 1) {
            #pragma unroll
            for (int p = 0; p < 4; p++) {
                s_lo[p] += __shfl_xor_sync(0xffffffffu, s_lo[p], o);
                s_hi[p] += __shfl_xor_sync(0xffffffffu, s_hi[p], o);
                q_lo[p] += __shfl_xor_sync(0xffffffffu, q_lo[p], o);
                q_hi[p] += __shfl_xor_sync(0xffffffffu, q_hi[p], o);
            }
        }
        float mu_lo[4], mu_hi[4], rs_lo[4], rs_hi[4];
        #pragma unroll
        for (int p = 0; p < 4; p++) {
            const float inv = 1.0f / (float)HID;
            mu_lo[p] = s_lo[p] * inv;
            mu_hi[p] = s_hi[p] * inv;
            float v0 = q_lo[p] * inv - mu_lo[p] * mu_lo[p];
            float v1 = q_hi[p] * inv - mu_hi[p] * mu_hi[p];
            rs_lo[p] = rsqrtf(v0 + LN_EPS_F);
            rs_hi[p] = rsqrtf(v1 + LN_EPS_F);
        }

        #pragma unroll
        for (int c = 0; c < 4; c++) {
            float w_ = sm[OFF_LNW + lane4 + c];
            float b_ = sm[OFF_LNB + lane4 + c];
            #pragma unroll
            for (int p = 0; p < 4; p++) {
                float lo, hi; unpack2(hacc[c][p], lo, hi);
                float nlo = fmaxf(fmaf((lo - mu_lo[p]) * rs_lo[p], w_, b_), 0.0f);
                float nhi = fmaxf(fmaf((hi - mu_hi[p]) * rs_hi[p], w_, b_), 0.0f);
                *(ull*)&sm[OFF_H + (lane4 + c) * TILE + ebase + 2 * p] = pack2(nlo, nhi);
            }
        }
        __syncwarp();

        // ---- GEMM2 ----------------------------------------------------------
        #pragma unroll
        for (int c = 0; c < 4; c++) {
            ull bd = dup2(sm[OFF_B2 + lane4 + c]);
            #pragma unroll
            for (int p = 0; p < 4; p++) acc[c][p] = add2(acc[c][p], bd);
        }
        #pragma unroll 8
        for (int k = 0; k < HID; k++) {
            GSTEP(acc, OFF_H + k * TILE, OFF_W2 + k * HID);
        }
    }

    #pragma unroll
    for (int p = 0; p < 4; p++) {
        float lo0, hi0, lo1, hi1, lo2, hi2, lo3, hi3;
        unpack2(acc[0][p], lo0, hi0);
        unpack2(acc[1][p], lo1, hi1);
        unpack2(acc[2][p], lo2, hi2);
        unpack2(acc[3][p], lo3, hi3);
        int e0 = tileBase + ebase + 2 * p;
        int e1 = e0 + 1;
        if (e0 < E_TOTAL) {
            float4 v = make_float4(lo0, lo1, lo2, lo3);
            *(float4*)&out[(size_t)e0 * HID + lane4] = v;
        }
        if (e1 < E_TOTAL) {
            float4 v = make_float4(hi0, hi1, hi2, hi3);
            *(float4*)&out[(size_t)e1 * HID + lane4] = v;
        }
    }
}

extern "C" void kernel_launch(void* const* d_in, const int* in_sizes, int n_in,
                              void* d_out, int out_size) {
    (void)in_sizes; (void)n_in; (void)out_size;
    const float* srcN  = (const float*)d_in[0];
    const float* tgtN  = (const float*)d_in[1];
    const void*  edge  = d_in[2];
    const float* freqs = (const float*)d_in[3];
    const float* W1    = (const float*)d_in[4];
    const float* b1    = (const float*)d_in[5];
    const float* lnw   = (const float*)d_in[6];
    const float* lnb   = (const float*)d_in[7];
    const float* W2    = (const float*)d_in[8];
    const float* b2    = (const float*)d_in[9];
    float* out = (float*)d_out;

    cudaFuncSetAttribute(rape_kernel,
                         cudaFuncAttributeMaxDynamicSharedMemorySize,
                         SMEM_FLOATS * (int)sizeof(float));

    detect_edge_dtype_kernel<<<1, 32>>>((const int2*)edge);

    int grid = (E_TOTAL + TILE - 1) / TILE;
    rape_kernel<<<grid, NTHREADS, SMEM_FLOATS * sizeof(float)>>>(
        srcN, tgtN, edge, freqs, W1, b1, lnw, lnb, W2, b2, out);
}